// round 3
// baseline (speedup 1.0000x reference)
#include <cuda_runtime.h>
#include <math.h>

#define NG   4
#define NB   6
#define NF   8
#define NFRR 256
#define NACT 5
#define BTOT 32768

typedef unsigned long long u64;

// ---------------- packed f32x2 helpers (Blackwell-only PTX) ----------------
__device__ __forceinline__ u64 pk(float lo, float hi) {
    u64 r; asm("mov.b64 %0,{%1,%2};" : "=l"(r) : "f"(lo), "f"(hi)); return r;
}
__device__ __forceinline__ void upk(u64 v, float& lo, float& hi) {
    asm("mov.b64 {%0,%1},%2;" : "=f"(lo), "=f"(hi) : "l"(v));
}
__device__ __forceinline__ u64 dup2(float v) { return pk(v, v); }
__device__ __forceinline__ u64 fma2(u64 a, u64 b, u64 c) {
    u64 d; asm("fma.rn.f32x2 %0,%1,%2,%3;" : "=l"(d) : "l"(a), "l"(b), "l"(c)); return d;
}
__device__ __forceinline__ u64 add2(u64 a, u64 b) {
    u64 d; asm("add.rn.f32x2 %0,%1,%2;" : "=l"(d) : "l"(a), "l"(b)); return d;
}
__device__ __forceinline__ u64 mul2(u64 a, u64 b) {
    u64 d; asm("mul.rn.f32x2 %0,%1,%2;" : "=l"(d) : "l"(a), "l"(b)); return d;
}
__device__ __forceinline__ u64 relu2(u64 a) {
    float lo, hi; upk(a, lo, hi);
    return pk(fmaxf(lo, 0.0f), fmaxf(hi, 0.0f));
}

// Precomputed factorization of relation similarity:
// sim[g,n,m]*16 = feat_n^T M_g feat_m + vt_g.feat_n + vp_g.feat_m + c_g
__device__ float g_M[NG][NF][NF];
__device__ float g_vt[NG][NF];
__device__ float g_vp[NG][NF];
__device__ float g_c[NG];

__global__ void precompute_kernel(const float* __restrict__ Wt,
                                  const float* __restrict__ bt,
                                  const float* __restrict__ Wp,
                                  const float* __restrict__ bp)
{
    int g   = blockIdx.x;
    int tid = threadIdx.x;            // 256 threads
    const float* wt = Wt + g * NFRR * NF;
    const float* wp = Wp + g * NFRR * NF;
    int ef = tid & 63;
    int q  = tid >> 6;                // 4 r-quarters
    int e  = ef >> 3, f = ef & 7;

    float acc = 0.f;
    int r0 = q * 64;
#pragma unroll 8
    for (int r = r0; r < r0 + 64; r++)
        acc = fmaf(wt[r * NF + e], wp[r * NF + f], acc);

    __shared__ float red[256];
    red[tid] = acc;
    __syncthreads();
    if (q == 0)
        g_M[g][e][f] = (red[ef] + red[64 + ef]) + (red[128 + ef] + red[192 + ef]);

    if (tid < NF) {
        float a = 0.f, c = 0.f;
        for (int r = 0; r < NFRR; r++) {
            a = fmaf(wt[r * NF + tid], bp[g * NFRR + r], a);
            c = fmaf(bt[g * NFRR + r], wp[r * NF + tid], c);
        }
        g_vt[g][tid] = a;
        g_vp[g][tid] = c;
    }
    if (tid == NF) {
        float cc = 0.f;
        for (int r = 0; r < NFRR; r++)
            cc = fmaf(bt[g * NFRR + r], bp[g * NFRR + r], cc);
        g_c[g] = cc;
    }
}

// 8 threads per batch-PAIR: lane sub = g*2 + nhalf.  Batches (2p, 2p+1) are
// packed in the two f32 halves of every u64 value.  65536 threads total.
__global__ __launch_bounds__(128) void gcn_kernel2(
    const float* __restrict__ X,     // [B,6,8]
    const float* __restrict__ P,     // [B,6,2]
    const float* __restrict__ Wext,  // [8,8]
    const float* __restrict__ bext,  // [8]
    const float* __restrict__ Wgcn,  // [4,8,8]
    const float* __restrict__ Wact,  // [5,8]
    const float* __restrict__ bact,  // [5]
    float* __restrict__ out)         // [B,5]
{
    // weights duplicated into both f32x2 halves; strides padded so the 4
    // g-lanes / 4 groups of a warp hit distinct banks.
    __shared__ u64 sWext2[64], sbext2[8];
    __shared__ u64 sM2[NG][66];
    __shared__ u64 svt2[NG][9], svp2[NG][9];
    __shared__ u64 sc2[NG];
    __shared__ u64 sWgcn2[NG][66];
    __shared__ u64 sWact2[40], sbact2[5];
    __shared__ u64 sFeat[16 * 50];   // per 8-lane group: feat[6][8], stride 50

    int tid = threadIdx.x;
    if (tid < 64) sWext2[tid] = dup2(Wext[tid]);
    if (tid < 8)  sbext2[tid] = dup2(bext[tid]);
    for (int i = tid; i < 256; i += 128) {
        sM2[i >> 6][i & 63]    = dup2(((const float*)g_M)[i]);
        sWgcn2[i >> 6][i & 63] = dup2(Wgcn[i]);
    }
    if (tid < 32) {
        svt2[tid >> 3][tid & 7] = dup2(((const float*)g_vt)[tid]);
        svp2[tid >> 3][tid & 7] = dup2(((const float*)g_vp)[tid]);
    }
    if (tid < 4)  sc2[tid] = dup2(g_c[tid]);
    if (tid < 40) sWact2[tid] = dup2(Wact[tid]);
    if (tid < 5)  sbact2[tid] = dup2(bact[tid]);

    int t    = blockIdx.x * 128 + tid;
    int pair = t >> 3;
    int sub  = t & 7;
    int g    = sub >> 1;
    int n0v  = (sub & 1) * 3;
    int b0   = pair * 2;
    u64* F   = &sFeat[(tid >> 3) * 50];

    const u64 ZERO2 = dup2(0.0f);

    // ---- pairwise distance masks (same op sequence as scalar ref) ----
    const float4* Pa = (const float4*)(P + b0 * 12);
    const float4* Pb = (const float4*)(P + (b0 + 1) * 12);
    float4 a0 = Pa[0], a1 = Pa[1], a2 = Pa[2];
    float4 c0 = Pb[0], c1 = Pb[1], c2 = Pb[2];
    float qx0[NB] = {a0.x, a0.z, a1.x, a1.z, a2.x, a2.z};
    float qy0[NB] = {a0.y, a0.w, a1.y, a1.w, a2.y, a2.w};
    float qx1[NB] = {c0.x, c0.z, c1.x, c1.z, c2.x, c2.z};
    float qy1[NB] = {c0.y, c0.w, c1.y, c1.w, c2.y, c2.w};
    u64 pxp[NB], pyp[NB], rrp[NB];
#pragma unroll
    for (int n = 0; n < NB; n++) {
        pxp[n] = pk(qx0[n], qx1[n]);
        pyp[n] = pk(qy0[n], qy1[n]);
        rrp[n] = fma2(pyp[n], pyp[n], mul2(pxp[n], pxp[n]));
    }
    const u64 NEG2 = dup2(-2.0f);
    unsigned msk0 = 0, msk1 = 0;  // bit (i*6+m) set => masked
#pragma unroll
    for (int i = 0; i < 3; i++) {
        int n = n0v + i;
#pragma unroll
        for (int m = 0; m < NB; m++) {
            u64 dotp = fma2(pyp[n], pyp[m], mul2(pxp[n], pxp[m]));
            u64 d2   = add2(fma2(dotp, NEG2, rrp[n]), rrp[m]);
            float dl, dh; upk(d2, dl, dh);
            if (__fsqrt_rn(dl) > 4.0f) msk0 |= 1u << (i * 6 + m);
            if (__fsqrt_rn(dh) > 4.0f) msk1 |= 1u << (i * 6 + m);
        }
    }

    __syncthreads();   // weight smem ready

    // ---- cooperative feature extension: lane computes 6 of 48 entries ----
    {
        int curn = -1;
        u64 xr[NF];
#pragma unroll
        for (int j = 0; j < 6; j++) {
            int i = sub * 6 + j;
            int n = i >> 3, f = i & 7;
            if (n != curn) {
                const float4* xa = (const float4*)(X + (b0 * NB + n) * NF);
                const float4* xb = (const float4*)(X + ((b0 + 1) * NB + n) * NF);
                float4 v0 = xa[0], v1 = xa[1], w0 = xb[0], w1 = xb[1];
                xr[0] = pk(v0.x, w0.x); xr[1] = pk(v0.y, w0.y);
                xr[2] = pk(v0.z, w0.z); xr[3] = pk(v0.w, w0.w);
                xr[4] = pk(v1.x, w1.x); xr[5] = pk(v1.y, w1.y);
                xr[6] = pk(v1.z, w1.z); xr[7] = pk(v1.w, w1.w);
                curn = n;
            }
            u64 acc = sbext2[f];
#pragma unroll
            for (int e = 0; e < NF; e++) acc = fma2(xr[e], sWext2[f * NF + e], acc);
            F[i] = relu2(acc);
        }
    }
    __syncthreads();   // feat ready

    // ---- sphi[m] = vp_g . feat_m  (per-thread, own g) ----
    u64 sphip[NB];
#pragma unroll
    for (int m = 0; m < NB; m++) {
        u64 acc = ZERO2;
#pragma unroll
        for (int f = 0; f < NF; f++) acc = fma2(svp2[g][f], F[m * NF + f], acc);
        sphip[m] = acc;
    }

    const u64 SC2 = dup2(0.0625f);
    u64 gs[3][NF];
#pragma unroll
    for (int i = 0; i < 3; i++)
#pragma unroll
        for (int f = 0; f < NF; f++) gs[i][f] = ZERO2;

#pragma unroll
    for (int i = 0; i < 3; i++) {
        int n = n0v + i;
        u64 Fn[NF];
#pragma unroll
        for (int e = 0; e < NF; e++) Fn[e] = F[n * NF + e];

        u64 tp[NF];
#pragma unroll
        for (int f = 0; f < NF; f++) {
            u64 acc = ZERO2;
#pragma unroll
            for (int e = 0; e < NF; e++) acc = fma2(Fn[e], sM2[g][e * NF + f], acc);
            tp[f] = acc;
        }
        u64 stp = sc2[g];
#pragma unroll
        for (int f = 0; f < NF; f++) stp = fma2(svt2[g][f], Fn[f], stp);

        float s0[NB], s1[NB];
#pragma unroll
        for (int m = 0; m < NB; m++) {
            u64 acc = add2(stp, sphip[m]);
#pragma unroll
            for (int f = 0; f < NF; f++) acc = fma2(tp[f], F[m * NF + f], acc);
            acc = mul2(acc, SC2);
            upk(acc, s0[m], s1[m]);
        }

        // per-lane scalar softmax
        unsigned rm0 = (msk0 >> (i * 6)) & 63u;
        unsigned rm1 = (msk1 >> (i * 6)) & 63u;
        float w0[NB], w1[NB];
        {
            float mx = -3.402823466e38f;
#pragma unroll
            for (int m = 0; m < NB; m++)
                if (!((rm0 >> m) & 1u)) mx = fmaxf(mx, s0[m]);
            float ps = 0.f;
#pragma unroll
            for (int m = 0; m < NB; m++) {
                float e_ = ((rm0 >> m) & 1u) ? 0.0f : __expf(s0[m] - mx);
                w0[m] = e_; ps += e_;
            }
            float inv = 1.0f / ps;
#pragma unroll
            for (int m = 0; m < NB; m++) w0[m] *= inv;
        }
        {
            float mx = -3.402823466e38f;
#pragma unroll
            for (int m = 0; m < NB; m++)
                if (!((rm1 >> m) & 1u)) mx = fmaxf(mx, s1[m]);
            float ps = 0.f;
#pragma unroll
            for (int m = 0; m < NB; m++) {
                float e_ = ((rm1 >> m) & 1u) ? 0.0f : __expf(s1[m] - mx);
                w1[m] = e_; ps += e_;
            }
            float inv = 1.0f / ps;
#pragma unroll
            for (int m = 0; m < NB; m++) w1[m] *= inv;
        }

        u64 ag[NF];
#pragma unroll
        for (int f = 0; f < NF; f++) ag[f] = ZERO2;
#pragma unroll
        for (int m = 0; m < NB; m++) {
            u64 wp = pk(w0[m], w1[m]);
#pragma unroll
            for (int f = 0; f < NF; f++) ag[f] = fma2(wp, F[m * NF + f], ag[f]);
        }
#pragma unroll
        for (int o = 0; o < NF; o++) {
            u64 acc = ZERO2;
#pragma unroll
            for (int f = 0; f < NF; f++) acc = fma2(ag[f], sWgcn2[g][o * NF + f], acc);
            gs[i][o] = add2(gs[i][o], relu2(acc));
        }
    }

    // ---- reduce gsum over the 4 g-lanes ----
#pragma unroll
    for (int i = 0; i < 3; i++)
#pragma unroll
        for (int f = 0; f < NF; f++)
            gs[i][f] = add2(gs[i][f], __shfl_xor_sync(0xffffffffu, gs[i][f], 2));
#pragma unroll
    for (int i = 0; i < 3; i++)
#pragma unroll
        for (int f = 0; f < NF; f++)
            gs[i][f] = add2(gs[i][f], __shfl_xor_sync(0xffffffffu, gs[i][f], 4));

    // ---- residual + max-pool over own 3 boxes ----
    const u64 Q2 = dup2(0.25f);
    float pl0[NF], pl1[NF];
#pragma unroll
    for (int f = 0; f < NF; f++) { pl0[f] = -3.402823466e38f; pl1[f] = -3.402823466e38f; }
#pragma unroll
    for (int i = 0; i < 3; i++) {
        int n = n0v + i;
        const float4* xa = (const float4*)(X + (b0 * NB + n) * NF);
        const float4* xb = (const float4*)(X + ((b0 + 1) * NB + n) * NF);
        float4 v0 = xa[0], v1 = xa[1], w0 = xb[0], w1 = xb[1];
        u64 xpk[NF] = {pk(v0.x, w0.x), pk(v0.y, w0.y), pk(v0.z, w0.z), pk(v0.w, w0.w),
                       pk(v1.x, w1.x), pk(v1.y, w1.y), pk(v1.z, w1.z), pk(v1.w, w1.w)};
#pragma unroll
        for (int f = 0; f < NF; f++) {
            u64 st2 = fma2(gs[i][f], Q2, xpk[f]);
            float lo, hi; upk(st2, lo, hi);
            pl0[f] = fmaxf(pl0[f], lo);
            pl1[f] = fmaxf(pl1[f], hi);
        }
    }

    // ---- combine the two n-halves ----
    u64 pooledp[NF];
#pragma unroll
    for (int f = 0; f < NF; f++) {
        u64 mine = pk(pl0[f], pl1[f]);
        u64 oth  = __shfl_xor_sync(0xffffffffu, mine, 1);
        float ol, oh; upk(oth, ol, oh);
        pooledp[f] = pk(fmaxf(pl0[f], ol), fmaxf(pl1[f], oh));
    }

    // ---- activity head (lane 0 of the 8-lane group writes both batches) ----
    if (sub == 0) {
        float* ob = out + b0 * NACT;
#pragma unroll
        for (int a = 0; a < NACT; a++) {
            u64 acc = sbact2[a];
#pragma unroll
            for (int f = 0; f < NF; f++) acc = fma2(pooledp[f], sWact2[a * NF + f], acc);
            float o0, o1; upk(acc, o0, o1);
            ob[a] = o0;
            ob[NACT + a] = o1;
        }
    }
}

extern "C" void kernel_launch(void* const* d_in, const int* in_sizes, int n_in,
                              void* d_out, int out_size)
{
    const float* X    = (const float*)d_in[0];
    const float* P    = (const float*)d_in[1];
    const float* Wext = (const float*)d_in[2];
    const float* bext = (const float*)d_in[3];
    const float* Wt   = (const float*)d_in[4];
    const float* bt   = (const float*)d_in[5];
    const float* Wp   = (const float*)d_in[6];
    const float* bp   = (const float*)d_in[7];
    const float* Wgcn = (const float*)d_in[8];
    const float* Wact = (const float*)d_in[9];
    const float* bact = (const float*)d_in[10];

    precompute_kernel<<<NG, 256>>>(Wt, bt, Wp, bp);
    gcn_kernel2<<<(BTOT / 2) * 8 / 128, 128>>>(X, P, Wext, bext, Wgcn, Wact, bact,
                                               (float*)d_out);
}

// round 4
// speedup vs baseline: 1.8087x; 1.8087x over previous
#include <cuda_runtime.h>
#include <math.h>

#define NG   4
#define NB   6
#define NF   8
#define NFRR 256
#define NACT 5
#define BTOT 32768

// Precomputed factorization of relation similarity:
// sim[g,n,m]*16 = feat_n^T M_g feat_m + vt_g.feat_n + vp_g.feat_m + c_g
__device__ float g_M[NG][NF * NF];
__device__ float g_vt[NG][NF];
__device__ float g_vp[NG][NF];
__device__ float g_c[NG];

__global__ void precompute_kernel(const float* __restrict__ Wt,
                                  const float* __restrict__ bt,
                                  const float* __restrict__ Wp,
                                  const float* __restrict__ bp)
{
    int g   = blockIdx.x;
    int tid = threadIdx.x;                 // 256 threads
    const float* wt  = Wt + g * NFRR * NF;
    const float* wp  = Wp + g * NFRR * NF;
    const float* btg = bt + g * NFRR;
    const float* bpg = bp + g * NFRR;
    __shared__ float red[256];

    // M[e][f] = sum_r wt[r][e] * wp[r][f]   (64 cells x 4 r-quarters)
    int ef = tid & 63, q = tid >> 6;
    int e  = ef >> 3,  f = ef & 7;
    float acc = 0.f;
#pragma unroll 8
    for (int r = q * 64; r < q * 64 + 64; r++)
        acc = fmaf(wt[r * NF + e], wp[r * NF + f], acc);
    red[tid] = acc;
    __syncthreads();
    if (q == 0)
        g_M[g][ef] = (red[ef] + red[64 + ef]) + (red[128 + ef] + red[192 + ef]);
    __syncthreads();

    // vt[f] = sum_r wt[r][f]*bp[r]; vp[f] = sum_r bt[r]*wp[r][f]; c = bt.bp
    float a2 = 0.f;
    if (tid < 64) {
        int ff = tid & 7, s = tid >> 3;
#pragma unroll 8
        for (int r = s * 32; r < s * 32 + 32; r++)
            a2 = fmaf(wt[r * NF + ff], bpg[r], a2);
        red[tid] = a2;
    } else if (tid < 128) {
        int id = tid - 64, ff = id & 7, s = id >> 3;
#pragma unroll 8
        for (int r = s * 32; r < s * 32 + 32; r++)
            a2 = fmaf(btg[r], wp[r * NF + ff], a2);
        red[tid] = a2;
    } else if (tid < 160) {
        int s = tid - 128;
#pragma unroll
        for (int r = s * 8; r < s * 8 + 8; r++)
            a2 = fmaf(btg[r], bpg[r], a2);
        red[tid] = a2;
    }
    __syncthreads();
    if (tid < 8) {
        float sm = 0.f;
        for (int s = 0; s < 8; s++) sm += red[s * 8 + tid];
        g_vt[g][tid] = sm;
    } else if (tid < 16) {
        int ff = tid - 8;
        float sm = 0.f;
        for (int s = 0; s < 8; s++) sm += red[64 + s * 8 + ff];
        g_vp[g][ff] = sm;
    } else if (tid == 16) {
        float sm = 0.f;
        for (int k = 0; k < 32; k++) sm += red[128 + k];
        g_c[g] = sm;
    }
}

// 2 threads per batch: half 0 owns boxes n=0..2, half 1 owns n=3..5.
// Each thread computes full feat + its 3 softmax rows end-to-end; the only
// cross-thread exchange is the final max-pool (shfl with partner lane).
__global__ __launch_bounds__(128, 3) void gcn_main(
    const float* __restrict__ X,     // [B,6,8]
    const float* __restrict__ P,     // [B,6,2]
    const float* __restrict__ Wext,  // [8,8]
    const float* __restrict__ bext,  // [8]
    const float* __restrict__ Wgcn,  // [4,8,8]
    const float* __restrict__ Wact,  // [5,8]
    const float* __restrict__ bact,  // [5]
    float* __restrict__ out)         // [B,5]
{
    __shared__ __align__(16) float sWext[64];
    __shared__ __align__(16) float sM[NG][64];
    __shared__ __align__(16) float sWgcn[NG][64];
    __shared__ __align__(16) float svt[NG][NF];
    __shared__ __align__(16) float svp[NG][NF];
    __shared__ __align__(16) float sWact[40];
    __shared__ float sbext[NF], sbact[NACT], sc[NG];

    int tid = threadIdx.x;
    if (tid < 64) sWext[tid] = Wext[tid];
    else if (tid < 104) sWact[tid - 64] = Wact[tid - 64];
    else if (tid < 112) sbext[tid - 104] = bext[tid - 104];
    else if (tid < 117) sbact[tid - 112] = bact[tid - 112];
    else if (tid < 121) sc[tid - 117] = g_c[tid - 117];
    for (int i = tid; i < 256; i += 128) {
        ((float*)sM)[i]    = ((const float*)g_M)[i];
        ((float*)sWgcn)[i] = Wgcn[i];
    }
    if (tid < 32) {
        ((float*)svt)[tid] = ((const float*)g_vt)[tid];
        ((float*)svp)[tid] = ((const float*)g_vp)[tid];
    }

    int t    = blockIdx.x * 128 + tid;
    int b    = t >> 1;
    int half = t & 1;
    int n0   = half * 3;

    // ---- pairwise distance mask for own 3 rows (exact R1 op sequence) ----
    const float4* P4 = (const float4*)(P + b * 12);
    float4 p0 = P4[0], p1 = P4[1], p2 = P4[2];
    float px[NB] = {p0.x, p0.z, p1.x, p1.z, p2.x, p2.z};
    float py[NB] = {p0.y, p0.w, p1.y, p1.w, p2.y, p2.w};
    float rr[NB];
#pragma unroll
    for (int n = 0; n < NB; n++)
        rr[n] = __fmaf_rn(py[n], py[n], __fmul_rn(px[n], px[n]));
    unsigned rowm[3];
#pragma unroll
    for (int i = 0; i < 3; i++) {
        int n = n0 + i;
        unsigned rm = 0;
#pragma unroll
        for (int m = 0; m < NB; m++) {
            float dot = __fmaf_rn(py[n], py[m], __fmul_rn(px[n], px[m]));
            float d2  = __fadd_rn(__fsub_rn(rr[n], __fmul_rn(2.0f, dot)), rr[m]);
            if (__fsqrt_rn(d2) > 4.0f) rm |= 1u << m;
        }
        rowm[i] = rm;
    }

    __syncthreads();   // weights staged

    // ---- feature extension: feat = relu(X @ Wext^T + bext), all 6 boxes ----
    const float4* X4 = (const float4*)(X + b * 48);
    float xr[NB][NF];
#pragma unroll
    for (int n = 0; n < NB; n++) {
        float4 a = X4[n * 2], c = X4[n * 2 + 1];
        xr[n][0] = a.x; xr[n][1] = a.y; xr[n][2] = a.z; xr[n][3] = a.w;
        xr[n][4] = c.x; xr[n][5] = c.y; xr[n][6] = c.z; xr[n][7] = c.w;
    }
    float feat[NB][NF];
#pragma unroll
    for (int f = 0; f < NF; f++) {
        float4 w0 = ((const float4*)&sWext[f * 8])[0];
        float4 w1 = ((const float4*)&sWext[f * 8])[1];
        float wr[NF] = {w0.x, w0.y, w0.z, w0.w, w1.x, w1.y, w1.z, w1.w};
        float bb = sbext[f];
#pragma unroll
        for (int n = 0; n < NB; n++) {
            float a = bb;
#pragma unroll
            for (int e = 0; e < NF; e++) a = fmaf(xr[n][e], wr[e], a);
            feat[n][f] = fmaxf(a, 0.0f);
        }
    }

    // ---- relation graphs, own 3 rows ----
    float gsum[3][NF];
#pragma unroll
    for (int i = 0; i < 3; i++)
#pragma unroll
        for (int f = 0; f < NF; f++) gsum[i][f] = 0.0f;

#pragma unroll
    for (int g = 0; g < NG; g++) {
        float4 v0 = ((const float4*)svp[g])[0];
        float4 v1 = ((const float4*)svp[g])[1];
        float vpr[NF] = {v0.x, v0.y, v0.z, v0.w, v1.x, v1.y, v1.z, v1.w};
        float sphi[NB];
#pragma unroll
        for (int m = 0; m < NB; m++) {
            float a = 0.f;
#pragma unroll
            for (int f = 0; f < NF; f++) a = fmaf(vpr[f], feat[m][f], a);
            sphi[m] = a;
        }

        // t[i][f] = sum_e feat[n0+i][e] * M[e][f]   (M rows broadcast once)
        float tt[3][NF];
#pragma unroll
        for (int i = 0; i < 3; i++)
#pragma unroll
            for (int f = 0; f < NF; f++) tt[i][f] = 0.f;
#pragma unroll
        for (int e = 0; e < NF; e++) {
            float4 m0 = ((const float4*)&sM[g][e * 8])[0];
            float4 m1 = ((const float4*)&sM[g][e * 8])[1];
            float mr[NF] = {m0.x, m0.y, m0.z, m0.w, m1.x, m1.y, m1.z, m1.w};
#pragma unroll
            for (int i = 0; i < 3; i++) {
                float fv = feat[n0 + i][e];
#pragma unroll
                for (int f = 0; f < NF; f++) tt[i][f] = fmaf(fv, mr[f], tt[i][f]);
            }
        }

        float4 u0 = ((const float4*)svt[g])[0];
        float4 u1 = ((const float4*)svt[g])[1];
        float vtr[NF] = {u0.x, u0.y, u0.z, u0.w, u1.x, u1.y, u1.z, u1.w};
        float cg = sc[g];

        float agg[3][NF];
#pragma unroll
        for (int i = 0; i < 3; i++) {
            float st = cg;
#pragma unroll
            for (int f = 0; f < NF; f++) st = fmaf(vtr[f], feat[n0 + i][f], st);

            float s[NB];
#pragma unroll
            for (int m = 0; m < NB; m++) {
                float a = st + sphi[m];
#pragma unroll
                for (int f = 0; f < NF; f++) a = fmaf(tt[i][f], feat[m][f], a);
                s[m] = a * 0.0625f;   // / sqrt(256)
            }

            unsigned rm = rowm[i];
            float mx = -3.402823466e38f;
#pragma unroll
            for (int m = 0; m < NB; m++)
                if (!((rm >> m) & 1u)) mx = fmaxf(mx, s[m]);
            float w[NB];
            float ps = 0.f;
#pragma unroll
            for (int m = 0; m < NB; m++) {
                float e_ = ((rm >> m) & 1u) ? 0.0f : __expf(s[m] - mx);
                w[m] = e_; ps += e_;
            }
            float inv = 1.0f / ps;

#pragma unroll
            for (int f = 0; f < NF; f++) agg[i][f] = 0.f;
#pragma unroll
            for (int m = 0; m < NB; m++) {
                float wv = w[m] * inv;
#pragma unroll
                for (int f = 0; f < NF; f++)
                    agg[i][f] = fmaf(wv, feat[m][f], agg[i][f]);
            }
        }

        // gcn: gsum[i][o] += relu(agg[i] . Wgcn[g][o])
#pragma unroll
        for (int o = 0; o < NF; o++) {
            float4 w0 = ((const float4*)&sWgcn[g][o * 8])[0];
            float4 w1 = ((const float4*)&sWgcn[g][o * 8])[1];
            float wr[NF] = {w0.x, w0.y, w0.z, w0.w, w1.x, w1.y, w1.z, w1.w};
#pragma unroll
            for (int i = 0; i < 3; i++) {
                float a = 0.f;
#pragma unroll
                for (int f = 0; f < NF; f++) a = fmaf(agg[i][f], wr[f], a);
                gsum[i][o] += fmaxf(a, 0.0f);
            }
        }
    }

    // ---- residual + max-pool over own 3 boxes ----
    float pl[NF];
#pragma unroll
    for (int f = 0; f < NF; f++) pl[f] = -3.402823466e38f;
#pragma unroll
    for (int i = 0; i < 3; i++) {
        int n = n0 + i;
        float4 a = X4[n * 2], c = X4[n * 2 + 1];
        float xv[NF] = {a.x, a.y, a.z, a.w, c.x, c.y, c.z, c.w};
#pragma unroll
        for (int f = 0; f < NF; f++)
            pl[f] = fmaxf(pl[f], fmaf(gsum[i][f], 0.25f, xv[f]));
    }

    // combine the two halves (partner lane differs in bit 0, same warp)
#pragma unroll
    for (int f = 0; f < NF; f++) {
        float o = __shfl_xor_sync(0xffffffffu, pl[f], 1);
        pl[f] = fmaxf(pl[f], o);
    }

    // ---- activity head ----
    if (half == 0) {
        float* ob = out + b * NACT;
#pragma unroll
        for (int a = 0; a < NACT; a++) {
            float acc = sbact[a];
#pragma unroll
            for (int f = 0; f < NF; f++) acc = fmaf(pl[f], sWact[a * 8 + f], acc);
            ob[a] = acc;
        }
    }
}

extern "C" void kernel_launch(void* const* d_in, const int* in_sizes, int n_in,
                              void* d_out, int out_size)
{
    const float* X    = (const float*)d_in[0];
    const float* P    = (const float*)d_in[1];
    const float* Wext = (const float*)d_in[2];
    const float* bext = (const float*)d_in[3];
    const float* Wt   = (const float*)d_in[4];
    const float* bt   = (const float*)d_in[5];
    const float* Wp   = (const float*)d_in[6];
    const float* bp   = (const float*)d_in[7];
    const float* Wgcn = (const float*)d_in[8];
    const float* Wact = (const float*)d_in[9];
    const float* bact = (const float*)d_in[10];

    precompute_kernel<<<NG, 256>>>(Wt, bt, Wp, bp);
    gcn_main<<<BTOT * 2 / 128, 128>>>(X, P, Wext, bext, Wgcn, Wact, bact,
                                      (float*)d_out);
}